// round 1
// baseline (speedup 1.0000x reference)
#include <cuda_runtime.h>

// Problem constants
#define Bc   8
#define Ac   60000
#define Cc   150           // 1 + (10+19+39+69+12)
#define Gc   20
#define Tc   5
#define BAc  (Bc * Ac)     // 480,000 anchors
#define NCONF (BAc * Cc)   // 72,000,000
#define NV4   (NCONF / 4)  // 18,000,000 float4s
#define NW    5            // 32-bit words per class-bitmask row (149 bits)
#define NROWS (Bc * (Gc + 1))   // 168 rows (row 0 per batch = zeros)

__device__ unsigned g_bits[NROWS * NW];
__device__ double   g_acc[3];   // [0]=reg_sum, [1]=cls_sum, [2]=num_pos

// ---------------------------------------------------------------------------
// Kernel 1: zero accumulators + build per-(b, group) class-presence bitmasks.
// Bit index = concatenated class index across the 5 heads (matches conf
// channels 1..149 after subtracting 1).
// ---------------------------------------------------------------------------
__global__ void init_kernel(const int* __restrict__ gt_labels) {
    int tid = threadIdx.x;
    if (tid < 3) g_acc[tid] = 0.0;
    // zero row 0 of each batch (pad row -> background / negative anchors)
    if (tid < Bc * NW) {
        int b = tid / NW, w = tid % NW;
        g_bits[(b * (Gc + 1)) * NW + w] = 0u;
    }
    // one thread per (b, g): OR together the T valid labels of each head
    if (tid < Bc * Gc) {
        int b = tid / Gc, g = tid % Gc;
        unsigned w[NW] = {0u, 0u, 0u, 0u, 0u};
        const int off[5] = {0, 10, 29, 68, 137};
#pragma unroll
        for (int h = 0; h < 5; h++) {
#pragma unroll
            for (int t = 0; t < Tc; t++) {
                int v = gt_labels[((b * Gc + g) * 5 + h) * Tc + t];
                if (v >= 0) {
                    int bit = off[h] + v;
                    w[bit >> 5] |= (1u << (bit & 31));
                }
            }
        }
#pragma unroll
        for (int k = 0; k < NW; k++)
            g_bits[(b * (Gc + 1) + (g + 1)) * NW + k] = w[k];
    }
}

// ---------------------------------------------------------------------------
// Focal term for one sigmoid logit x with binary label l.
//   l=1: -log(p)   * 0.25 * (1-p)^2
//   l=0: -log(1-p) * 0.75 * p^2          with p = sigmoid(x)
// Unified via s = l ? -x : x, q = sigma(s), term = a' * softplus(s) * q^2.
// MUFU ops: EX2, RCP, LG2 (r = 1/(1+e^s) shared between q and softplus).
// ---------------------------------------------------------------------------
__device__ __forceinline__ float focal_term(float x, int c, int b, int lb,
                                            const unsigned* __restrict__ sb) {
    int l;
    if (c == 0) {
        l = (lb > 0) ? 1 : 0;               // binary head vs pos
    } else {
        int cb = c - 1;                     // lb >= 0 guaranteed by caller
        l = (int)((sb[(b * (Gc + 1) + lb) * NW + (cb >> 5)] >> (cb & 31)) & 1u);
    }
    float s  = l ? -x : x;
    float ap = l ? 0.25f : 0.75f;
    float u  = __expf(s);                       // EX2
    float r  = __fdividef(1.0f, 1.0f + u);      // RCP : r = 1 - sigma(s)
    float q  = 1.0f - r;                        // sigma(s)
    float sp = -__logf(r);                      // LG2 : softplus(s) = -log(r)
    return ap * sp * q * q;
}

// ---------------------------------------------------------------------------
// Kernel 2: one pass over everything.
//   - focal loss over 18M float4s of confidence
//   - smooth-L1 regression + pos count over 480k anchors
// Accumulate per-thread fp32, block-reduce, 3 double atomics per block.
// ---------------------------------------------------------------------------
__global__ void __launch_bounds__(256)
main_kernel(const float4* __restrict__ conf4,
            const float4* __restrict__ pred4,
            const float4* __restrict__ gt4,
            const int*    __restrict__ labels_bin) {
    __shared__ unsigned sb[NROWS * NW];
    for (int i = threadIdx.x; i < NROWS * NW; i += blockDim.x)
        sb[i] = g_bits[i];
    __syncthreads();

    const int tid    = blockIdx.x * blockDim.x + threadIdx.x;
    const int stride = gridDim.x * blockDim.x;

    float cls = 0.0f, reg = 0.0f, npos = 0.0f;

    // ---- classification: grid-stride over float4s of confidence ----
    for (int i = tid; i < NV4; i += stride) {
        float4 v  = conf4[i];
        int base  = i << 2;
        int a     = base / Cc;
        int c     = base - a * Cc;
        int b     = a / Ac;
        int lb    = labels_bin[a];
        float xs[4] = {v.x, v.y, v.z, v.w};
#pragma unroll
        for (int k = 0; k < 4; k++) {
            if (lb >= 0) cls += focal_term(xs[k], c, b, lb, sb);
            if (++c == Cc) {           // crossed to next anchor
                c = 0;
                a++;
                if (k < 3) {           // avoid OOB read at the very end
                    b  = a / Ac;
                    lb = labels_bin[a];
                }
            }
        }
    }

    // ---- regression + pos count: grid-stride over anchors ----
    for (int a = tid; a < BAc; a += stride) {
        int lb = labels_bin[a];
        if (lb > 0) {
            npos += 1.0f;
            float4 p = pred4[a];
            float4 g = gt4[a];
            float d[4] = {p.x - g.x, p.y - g.y, p.z - g.z, p.w - g.w};
#pragma unroll
            for (int k = 0; k < 4; k++) {
                float n = fabsf(d[k]);
                // BETA = 1/9 : n < B ? 0.5 n^2/B : n - 0.5 B
                reg += (n < (1.0f / 9.0f)) ? 4.5f * n * n
                                           : n - (1.0f / 18.0f);
            }
        }
    }

    // ---- block reduction (8 warps of 32) ----
#pragma unroll
    for (int o = 16; o > 0; o >>= 1) {
        cls  += __shfl_down_sync(0xFFFFFFFFu, cls,  o);
        reg  += __shfl_down_sync(0xFFFFFFFFu, reg,  o);
        npos += __shfl_down_sync(0xFFFFFFFFu, npos, o);
    }
    __shared__ float red[3][8];
    int warp = threadIdx.x >> 5, lane = threadIdx.x & 31;
    if (lane == 0) { red[0][warp] = reg; red[1][warp] = cls; red[2][warp] = npos; }
    __syncthreads();
    if (threadIdx.x == 0) {
        float r0 = 0.f, r1 = 0.f, r2 = 0.f;
#pragma unroll
        for (int w = 0; w < 8; w++) { r0 += red[0][w]; r1 += red[1][w]; r2 += red[2][w]; }
        atomicAdd(&g_acc[0], (double)r0);
        atomicAdd(&g_acc[1], (double)r1);
        atomicAdd(&g_acc[2], (double)r2);
    }
}

// ---------------------------------------------------------------------------
// Kernel 3: finalize.
//   out[0] = reg_sum / (num_pos * 4)
//   out[1] = cls_sum / (num_pos * 6)
// ---------------------------------------------------------------------------
__global__ void finalize_kernel(float* __restrict__ out) {
    double np = g_acc[2];
    if (np < 1.0) np = 1.0;
    out[0] = (float)(g_acc[0] / (np * 4.0));
    out[1] = (float)(g_acc[1] / (np * 6.0));
}

extern "C" void kernel_launch(void* const* d_in, const int* in_sizes, int n_in,
                              void* d_out, int out_size) {
    const float* conf       = (const float*)d_in[0];   // (8, 60000, 150) f32
    const float* pred       = (const float*)d_in[1];   // (8, 60000, 4)   f32
    const float* gt_loc     = (const float*)d_in[2];   // (8, 60000, 4)   f32
    const int*   gt_labels  = (const int*)  d_in[3];   // (8, 20, 5, 5)   i32
    // d_in[4] = counts: unused by the reference computation
    const int*   labels_bin = (const int*)  d_in[5];   // (8, 60000)      i32
    float* out = (float*)d_out;

    init_kernel<<<1, 256>>>(gt_labels);

    int grid = 2048;
    main_kernel<<<grid, 256>>>((const float4*)conf,
                               (const float4*)pred,
                               (const float4*)gt_loc,
                               labels_bin);

    finalize_kernel<<<1, 1>>>(out);
}

// round 2
// speedup vs baseline: 1.3225x; 1.3225x over previous
#include <cuda_runtime.h>

// ---------------------------------------------------------------------------
// Problem constants
// ---------------------------------------------------------------------------
#define Bc    8
#define Ac    60000
#define Cc    150                 // 1 + (10+19+39+69+12)
#define Gc    20
#define Tc    5
#define BAc   (Bc * Ac)           // 480,000 anchors
#define NCONF (BAc * Cc)          // 72,000,000
#define NV4   (NCONF / 4)         // 18,000,000 float4s
#define RW    8                   // padded words per bitmask row (150 bits -> 5 words + pad)
#define NROWS (Bc * (Gc + 1))     // 168 rows

__device__ unsigned g_bits[NROWS * RW];
__device__ double   g_acc[3];     // [0]=reg_sum, [1]=cls_sum, [2]=num_pos

// ---------------------------------------------------------------------------
// Kernel 1: build per-(b, lb) 150-bit label masks.
//   bit 0      = (lb > 0)                       (binary head label)
//   bit 1+k    = class-k present in group lb-1  (concatenated across 5 heads)
// Row lb=0 is all zeros (pad row). Each word written by exactly one thread.
// ---------------------------------------------------------------------------
__global__ void init_kernel(const int* __restrict__ gt_labels) {
    int tid = threadIdx.x;
    if (tid < 3) g_acc[tid] = 0.0;
    if (tid < NROWS) {
        int b = tid / (Gc + 1), g = tid % (Gc + 1);
        unsigned w[RW] = {0u, 0u, 0u, 0u, 0u, 0u, 0u, 0u};
        if (g > 0) {
            w[0] = 1u;                            // bit 0: lb>0 -> positive
            const int off[5] = {1, 11, 30, 69, 138};  // 1 + head offsets
            int grp = g - 1;
#pragma unroll
            for (int h = 0; h < 5; h++) {
#pragma unroll
                for (int t = 0; t < Tc; t++) {
                    int v = gt_labels[((b * Gc + grp) * 5 + h) * Tc + t];
                    if (v >= 0) {
                        int bit = off[h] + v;
                        w[bit >> 5] |= (1u << (bit & 31));
                    }
                }
            }
        }
#pragma unroll
        for (int k = 0; k < RW; k++)
            g_bits[tid * RW + k] = w[k];
    }
}

// ---------------------------------------------------------------------------
// Branchless focal term. Single MUFU chain (EX2, RCP, LG2) serves both labels:
//   u = e^x, r = 1/(1+u), sp = log(1+u) = -log(r)
//   l=0:  0.75 * sp       * (1-r)^2
//   l=1:  0.25 * (sp - x) * r^2
// ---------------------------------------------------------------------------
__device__ __forceinline__ void focal(float x, bool l, float m, float& acc) {
    float u  = __expf(x);                      // EX2 (+1 FMUL)
    float r  = __fdividef(1.0f, 1.0f + u);     // RCP
    float sp = -__logf(r);                     // LG2 (+1 FMUL)
    float S  = l ? sp - x : sp;
    float R  = l ? r      : 1.0f - r;
    float A  = l ? 0.25f  : 0.75f;
    acc = fmaf(A * m, S * R * R, acc);
}

// ---------------------------------------------------------------------------
// Kernel 2: fused single pass.
// ---------------------------------------------------------------------------
__global__ void __launch_bounds__(256)
main_kernel(const float4* __restrict__ conf4,
            const float4* __restrict__ pred4,
            const float4* __restrict__ gt4,
            const int*    __restrict__ lbin) {
    __shared__ unsigned sb[NROWS * RW];        // 5.25 KB
    for (int i = threadIdx.x; i < NROWS * RW; i += 256)
        sb[i] = g_bits[i];
    __syncthreads();

    const int tid    = blockIdx.x * 256 + threadIdx.x;
    const int stride = gridDim.x * 256;

    float cls0 = 0.f, cls1 = 0.f, reg = 0.f, npos = 0.f;

    // ---- classification over 18M float4s ----
#pragma unroll 2
    for (int i = tid; i < NV4; i += stride) {
        float4 v = conf4[i];
        unsigned base = (unsigned)i << 2;
        unsigned a = base / (unsigned)Cc;       // magic-mul division
        int c = (int)(base - a * Cc);           // even, 0..148
        unsigned b = a / (unsigned)Ac;
        int lb = __ldg(&lbin[a]);
        int row = (int)b * (Gc + 1) + max(lb, 0);

        const unsigned* rp = &sb[row * RW + (c >> 5)];
        unsigned bits = __funnelshift_r(rp[0], rp[1], c);  // low 4 bits = labels
        float m01 = (lb >= 0) ? 1.f : 0.f;
        float m23 = m01;

        if (c == 148) {                         // anchor crossing: 2+2 split
            unsigned a2 = a + 1;
            int lb2 = __ldg(&lbin[a2]);
            unsigned b2 = a2 / (unsigned)Ac;
            int row2 = (int)b2 * (Gc + 1) + max(lb2, 0);
            bits = (bits & 3u) | ((sb[row2 * RW] & 3u) << 2);
            m23 = (lb2 >= 0) ? 1.f : 0.f;
        }

        focal(v.x, (bits      & 1u) != 0u, m01, cls0);
        focal(v.y, ((bits>>1) & 1u) != 0u, m01, cls1);
        focal(v.z, ((bits>>2) & 1u) != 0u, m23, cls0);
        focal(v.w, ((bits>>3) & 1u) != 0u, m23, cls1);
    }

    // ---- regression + pos count over 480k anchors ----
    for (int a = tid; a < BAc; a += stride) {
        int lb = __ldg(&lbin[a]);
        if (lb > 0) {
            npos += 1.0f;
            float4 p = pred4[a];
            float4 g = gt4[a];
            float d[4] = {p.x - g.x, p.y - g.y, p.z - g.z, p.w - g.w};
#pragma unroll
            for (int k = 0; k < 4; k++) {
                float n = fabsf(d[k]);
                reg += (n < (1.0f / 9.0f)) ? 4.5f * n * n : n - (1.0f / 18.0f);
            }
        }
    }

    // ---- block reduction ----
    float cls = cls0 + cls1;
#pragma unroll
    for (int o = 16; o > 0; o >>= 1) {
        cls  += __shfl_down_sync(0xFFFFFFFFu, cls,  o);
        reg  += __shfl_down_sync(0xFFFFFFFFu, reg,  o);
        npos += __shfl_down_sync(0xFFFFFFFFu, npos, o);
    }
    __shared__ float red[3][8];
    int warp = threadIdx.x >> 5, lane = threadIdx.x & 31;
    if (lane == 0) { red[0][warp] = reg; red[1][warp] = cls; red[2][warp] = npos; }
    __syncthreads();
    if (threadIdx.x == 0) {
        float r0 = 0.f, r1 = 0.f, r2 = 0.f;
#pragma unroll
        for (int w = 0; w < 8; w++) { r0 += red[0][w]; r1 += red[1][w]; r2 += red[2][w]; }
        atomicAdd(&g_acc[0], (double)r0);
        atomicAdd(&g_acc[1], (double)r1);
        atomicAdd(&g_acc[2], (double)r2);
    }
}

// ---------------------------------------------------------------------------
// Kernel 3: finalize.
// ---------------------------------------------------------------------------
__global__ void finalize_kernel(float* __restrict__ out) {
    double np = g_acc[2];
    if (np < 1.0) np = 1.0;
    out[0] = (float)(g_acc[0] / (np * 4.0));
    out[1] = (float)(g_acc[1] / (np * 6.0));
}

extern "C" void kernel_launch(void* const* d_in, const int* in_sizes, int n_in,
                              void* d_out, int out_size) {
    const float* conf       = (const float*)d_in[0];   // (8, 60000, 150) f32
    const float* pred       = (const float*)d_in[1];   // (8, 60000, 4)   f32
    const float* gt_loc     = (const float*)d_in[2];   // (8, 60000, 4)   f32
    const int*   gt_labels  = (const int*)  d_in[3];   // (8, 20, 5, 5)   i32
    // d_in[4] = counts: not used by the computation
    const int*   labels_bin = (const int*)  d_in[5];   // (8, 60000)      i32
    float* out = (float*)d_out;

    init_kernel<<<1, 256>>>(gt_labels);

    main_kernel<<<2048, 256>>>((const float4*)conf,
                               (const float4*)pred,
                               (const float4*)gt_loc,
                               labels_bin);

    finalize_kernel<<<1, 1>>>(out);
}